// round 1
// baseline (speedup 1.0000x reference)
#include <cuda_runtime.h>
#include <cuda_bf16.h>
#include <float.h>

// Problem constants
#define NQ    65536      // number of query vectors (32*2048)
#define NE    4096       // codebook entries
#define ED    256        // embedding dim
#define BM    128        // queries per block
#define BN    128        // codes per tile
#define BK    16         // k-slice per stage
#define NTILE (NE / BN)  // 32
#define NSTG  (ED / BK)  // 16
#define BSS   132        // padded smem stride for code tile

// Scratch (no allocations allowed)
__device__ float g_A[NQ];
__device__ float g_B[NE];

// ---------------------------------------------------------------------------
// Row sums of squares, mirroring XLA-CPU scalar sequential reduction:
// acc = fadd(acc, fmul(v,v)) in strict element order (no fma, no reassoc).
// ---------------------------------------------------------------------------
__global__ void rowsq_z(const float4* __restrict__ z4) {
    int n = blockIdx.x * blockDim.x + threadIdx.x;
    if (n >= NQ) return;
    const float4* p = z4 + (size_t)n * (ED / 4);
    float acc = 0.0f;
    #pragma unroll 8
    for (int i = 0; i < ED / 4; i++) {
        float4 v = __ldg(p + i);
        acc = __fadd_rn(acc, __fmul_rn(v.x, v.x));
        acc = __fadd_rn(acc, __fmul_rn(v.y, v.y));
        acc = __fadd_rn(acc, __fmul_rn(v.z, v.z));
        acc = __fadd_rn(acc, __fmul_rn(v.w, v.w));
    }
    g_A[n] = acc;
}

__global__ void rowsq_cb(const float4* __restrict__ c4) {
    int n = blockIdx.x * blockDim.x + threadIdx.x;
    if (n >= NE) return;
    const float4* p = c4 + (size_t)n * (ED / 4);
    float acc = 0.0f;
    #pragma unroll 8
    for (int i = 0; i < ED / 4; i++) {
        float4 v = __ldg(p + i);
        acc = __fadd_rn(acc, __fmul_rn(v.x, v.x));
        acc = __fadd_rn(acc, __fmul_rn(v.y, v.y));
        acc = __fadd_rn(acc, __fmul_rn(v.z, v.z));
        acc = __fadd_rn(acc, __fmul_rn(v.w, v.w));
    }
    g_B[n] = acc;
}

// ---------------------------------------------------------------------------
// Main kernel: per 128-query block, stream all 4096 codes, maintain running
// argmin of d = fl(fl(A+B) - 2*dot), dot accumulated via fmaf k=0..255
// sequentially (mirrors Eigen gebp). Gather of winning codebook rows fused.
// ---------------------------------------------------------------------------
__global__ void __launch_bounds__(256, 1)
vq_main(const float* __restrict__ z, const float* __restrict__ cb,
        float* __restrict__ out) {
    extern __shared__ float sm[];
    float* zs = sm;                      // [ED][BM] = 256*128 floats (128KB)
    float* bs = sm + ED * BM;            // [2][BK][BSS]
    int*  sidx = (int*)bs;               // reused after main loop

    const int tid = threadIdx.x;
    const int tx = tid & 15;             // code sub-tile  (8 codes)
    const int ty = tid >> 4;             // query sub-tile (8 queries)
    const int q0 = blockIdx.x * BM;

    const float4* z4  = (const float4*)z;
    const float4* cb4 = (const float4*)cb;

    // --- stage z block into smem, transposed to [k][m] ---
    for (int e = tid; e < BM * (ED / 4); e += 256) {
        int m = e & (BM - 1);
        int kq = e >> 7;                 // 0..63 (float4 index along d)
        float4 v = __ldg(z4 + (size_t)(q0 + m) * (ED / 4) + kq);
        zs[(4 * kq + 0) * BM + m] = v.x;
        zs[(4 * kq + 1) * BM + m] = v.y;
        zs[(4 * kq + 2) * BM + m] = v.z;
        zs[(4 * kq + 3) * BM + m] = v.w;
    }

    float Aval[8];
    #pragma unroll
    for (int i = 0; i < 8; i++) Aval[i] = g_A[q0 + ty * 8 + i];

    float best[8];
    int   bidx[8];
    #pragma unroll
    for (int i = 0; i < 8; i++) { best[i] = FLT_MAX; bidx[i] = 0; }

    __syncthreads();

    for (int ct = 0; ct < NTILE; ct++) {
        const int c0 = ct * BN;

        float Bv[8];
        #pragma unroll
        for (int j = 0; j < 8; j++) Bv[j] = g_B[c0 + tx * 8 + j];

        float acc[8][8];
        #pragma unroll
        for (int i = 0; i < 8; i++)
            #pragma unroll
            for (int j = 0; j < 8; j++) acc[i][j] = 0.0f;

        // register double-buffer for code tiles
        float4 ra, rb;
        const int code0 = tid >> 2, kq0 = tid & 3;             // e = tid
        const int code1 = (tid + 256) >> 2, kq1 = (tid + 256) & 3;

        // prefetch stage 0
        ra = __ldg(cb4 + (size_t)(c0 + code0) * (ED / 4) + kq0);
        rb = __ldg(cb4 + (size_t)(c0 + code1) * (ED / 4) + kq1);
        {
            float* dst = bs;  // buf 0
            dst[(kq0 * 4 + 0) * BSS + code0] = ra.x;
            dst[(kq0 * 4 + 1) * BSS + code0] = ra.y;
            dst[(kq0 * 4 + 2) * BSS + code0] = ra.z;
            dst[(kq0 * 4 + 3) * BSS + code0] = ra.w;
            dst[(kq1 * 4 + 0) * BSS + code1] = rb.x;
            dst[(kq1 * 4 + 1) * BSS + code1] = rb.y;
            dst[(kq1 * 4 + 2) * BSS + code1] = rb.z;
            dst[(kq1 * 4 + 3) * BSS + code1] = rb.w;
        }
        __syncthreads();

        for (int s = 0; s < NSTG; s++) {
            if (s < NSTG - 1) {
                ra = __ldg(cb4 + (size_t)(c0 + code0) * (ED / 4) + (s + 1) * 4 + kq0);
                rb = __ldg(cb4 + (size_t)(c0 + code1) * (ED / 4) + (s + 1) * 4 + kq1);
            }
            const float* bcur = bs + (s & 1) * BK * BSS;
            const int kbase = s * BK;
            #pragma unroll
            for (int kk = 0; kk < BK; kk++) {
                const int k = kbase + kk;
                float a[8], b[8];
                float4 t;
                t = *(const float4*)&zs[k * BM + ty * 8];
                a[0] = t.x; a[1] = t.y; a[2] = t.z; a[3] = t.w;
                t = *(const float4*)&zs[k * BM + ty * 8 + 4];
                a[4] = t.x; a[5] = t.y; a[6] = t.z; a[7] = t.w;
                t = *(const float4*)&bcur[kk * BSS + tx * 8];
                b[0] = t.x; b[1] = t.y; b[2] = t.z; b[3] = t.w;
                t = *(const float4*)&bcur[kk * BSS + tx * 8 + 4];
                b[4] = t.x; b[5] = t.y; b[6] = t.z; b[7] = t.w;
                #pragma unroll
                for (int i = 0; i < 8; i++)
                    #pragma unroll
                    for (int j = 0; j < 8; j++)
                        acc[i][j] = fmaf(a[i], b[j], acc[i][j]);
            }
            __syncthreads();
            if (s < NSTG - 1) {
                float* dst = bs + ((s + 1) & 1) * BK * BSS;
                dst[(kq0 * 4 + 0) * BSS + code0] = ra.x;
                dst[(kq0 * 4 + 1) * BSS + code0] = ra.y;
                dst[(kq0 * 4 + 2) * BSS + code0] = ra.z;
                dst[(kq0 * 4 + 3) * BSS + code0] = ra.w;
                dst[(kq1 * 4 + 0) * BSS + code1] = rb.x;
                dst[(kq1 * 4 + 1) * BSS + code1] = rb.y;
                dst[(kq1 * 4 + 2) * BSS + code1] = rb.z;
                dst[(kq1 * 4 + 3) * BSS + code1] = rb.w;
                __syncthreads();
            }
        }

        // epilogue: d = fl(fl(A+B) - 2*dot), running argmin (first-index ties)
        #pragma unroll
        for (int i = 0; i < 8; i++) {
            #pragma unroll
            for (int j = 0; j < 8; j++) {
                float v = __fsub_rn(__fadd_rn(Aval[i], Bv[j]),
                                    __fmul_rn(2.0f, acc[i][j]));
                int col = c0 + tx * 8 + j;
                if (v < best[i]) { best[i] = v; bidx[i] = col; }
            }
        }
    }

    // cross-tx reduction: 16 lanes (same ty) live in one half-warp
    #pragma unroll
    for (int i = 0; i < 8; i++) {
        float v = best[i];
        int ix = bidx[i];
        #pragma unroll
        for (int off = 8; off > 0; off >>= 1) {
            float ov = __shfl_xor_sync(0xFFFFFFFFu, v, off);
            int   oi = __shfl_xor_sync(0xFFFFFFFFu, ix, off);
            if (ov < v || (ov == v && oi < ix)) { v = ov; ix = oi; }
        }
        if (tx == 0) sidx[ty * 8 + i] = ix;
    }
    __syncthreads();

    // fused gather: out[q0+r, :] = codebook[sidx[r], :]
    float4* out4 = (float4*)out;
    for (int e = tid; e < BM * (ED / 4); e += 256) {
        int r = e >> 6;
        int c = e & 63;
        out4[(size_t)(q0 + r) * (ED / 4) + c] =
            __ldg(cb4 + (size_t)sidx[r] * (ED / 4) + c);
    }
}

// ---------------------------------------------------------------------------
extern "C" void kernel_launch(void* const* d_in, const int* in_sizes, int n_in,
                              void* d_out, int out_size) {
    const float* z  = (const float*)d_in[0];   // [32,2048,256] f32
    const float* cb = (const float*)d_in[1];   // [4096,256] f32
    float* out = (float*)d_out;

    const int smem_bytes = (ED * BM + 2 * BK * BSS) * (int)sizeof(float);
    cudaFuncSetAttribute(vq_main, cudaFuncAttributeMaxDynamicSharedMemorySize,
                         smem_bytes);

    rowsq_z <<<NQ / 256, 256>>>((const float4*)z);
    rowsq_cb<<<NE / 256, 256>>>((const float4*)cb);
    vq_main <<<NQ / BM, 256, smem_bytes>>>(z, cb, out);
}

// round 2
// speedup vs baseline: 1.0140x; 1.0140x over previous
#include <cuda_runtime.h>
#include <cuda_bf16.h>
#include <float.h>

// Problem constants
#define NQ    65536      // number of query vectors (32*2048)
#define NE    4096       // codebook entries
#define ED    256        // embedding dim
#define BM    128        // queries per block
#define BN    128        // codes per tile
#define BK    16         // k-slice per stage
#define NTILE (NE / BN)  // 32
#define NSTG  (ED / BK)  // 16
#define BSS   132        // padded smem stride for code tile

// Scratch (no allocations allowed)
__device__ float g_A[NQ];
__device__ float g_B[NE];

// Packed f32x2 FMA: two independent IEEE fp32 rn FMAs per instruction.
// Bit-exact per lane vs fmaf — preserves the reference-matching numerics.
__device__ __forceinline__ void ffma2(unsigned long long& d,
                                      unsigned long long a,
                                      unsigned long long b) {
    asm volatile("fma.rn.f32x2 %0, %1, %2, %0;" : "+l"(d) : "l"(a), "l"(b));
}
__device__ __forceinline__ unsigned long long pack2(float x, float y) {
    unsigned long long r;
    asm("mov.b64 %0, {%1, %2};" : "=l"(r) : "f"(x), "f"(y));
    return r;
}
__device__ __forceinline__ void unpack2(float& x, float& y, unsigned long long p) {
    asm("mov.b64 {%0, %1}, %2;" : "=f"(x), "=f"(y) : "l"(p));
}

// ---------------------------------------------------------------------------
// Row sums of squares, mirroring XLA-CPU scalar sequential reduction:
// acc = fadd(acc, fmul(v,v)) in strict element order (no fma, no reassoc).
// ---------------------------------------------------------------------------
__global__ void rowsq_z(const float4* __restrict__ z4) {
    int n = blockIdx.x * blockDim.x + threadIdx.x;
    if (n >= NQ) return;
    const float4* p = z4 + (size_t)n * (ED / 4);
    float acc = 0.0f;
    #pragma unroll 8
    for (int i = 0; i < ED / 4; i++) {
        float4 v = __ldg(p + i);
        acc = __fadd_rn(acc, __fmul_rn(v.x, v.x));
        acc = __fadd_rn(acc, __fmul_rn(v.y, v.y));
        acc = __fadd_rn(acc, __fmul_rn(v.z, v.z));
        acc = __fadd_rn(acc, __fmul_rn(v.w, v.w));
    }
    g_A[n] = acc;
}

__global__ void rowsq_cb(const float4* __restrict__ c4) {
    int n = blockIdx.x * blockDim.x + threadIdx.x;
    if (n >= NE) return;
    const float4* p = c4 + (size_t)n * (ED / 4);
    float acc = 0.0f;
    #pragma unroll 8
    for (int i = 0; i < ED / 4; i++) {
        float4 v = __ldg(p + i);
        acc = __fadd_rn(acc, __fmul_rn(v.x, v.x));
        acc = __fadd_rn(acc, __fmul_rn(v.y, v.y));
        acc = __fadd_rn(acc, __fmul_rn(v.z, v.z));
        acc = __fadd_rn(acc, __fmul_rn(v.w, v.w));
    }
    g_B[n] = acc;
}

// ---------------------------------------------------------------------------
// Main kernel: per 128-query block, stream all 4096 codes, maintain running
// argmin of d = fl(fl(A+B) - 2*dot). Dot accumulated k=0..255 sequentially,
// one FMA chain per (query, code) — now packed 2-wide via fma.rn.f32x2
// (FFMA2), which doubles fp32 FMA issue rate on sm_103a (FFMA-3reg is rt=2).
// ---------------------------------------------------------------------------
__global__ void __launch_bounds__(256, 1)
vq_main(const float* __restrict__ z, const float* __restrict__ cb,
        float* __restrict__ out) {
    extern __shared__ float sm[];
    float* zs = sm;                      // [ED][BM] = 256*128 floats (128KB)
    float* bs = sm + ED * BM;            // [2][BK][BSS]
    int*  sidx = (int*)bs;               // reused after main loop

    const int tid = threadIdx.x;
    const int tx = tid & 15;             // code sub-tile  (8 codes)
    const int ty = tid >> 4;             // query sub-tile (8 queries)
    const int q0 = blockIdx.x * BM;

    const float4* z4  = (const float4*)z;
    const float4* cb4 = (const float4*)cb;

    // --- stage z block into smem, transposed to [k][m] ---
    for (int e = tid; e < BM * (ED / 4); e += 256) {
        int m = e & (BM - 1);
        int kq = e >> 7;                 // 0..63 (float4 index along d)
        float4 v = __ldg(z4 + (size_t)(q0 + m) * (ED / 4) + kq);
        zs[(4 * kq + 0) * BM + m] = v.x;
        zs[(4 * kq + 1) * BM + m] = v.y;
        zs[(4 * kq + 2) * BM + m] = v.z;
        zs[(4 * kq + 3) * BM + m] = v.w;
    }

    float Aval[8];
    #pragma unroll
    for (int i = 0; i < 8; i++) Aval[i] = g_A[q0 + ty * 8 + i];

    float best[8];
    int   bidx[8];
    #pragma unroll
    for (int i = 0; i < 8; i++) { best[i] = FLT_MAX; bidx[i] = 0; }

    __syncthreads();

    for (int ct = 0; ct < NTILE; ct++) {
        const int c0 = ct * BN;

        float Bv[8];
        #pragma unroll
        for (int j = 0; j < 8; j++) Bv[j] = g_B[c0 + tx * 8 + j];

        // 8 queries x 4 code-pairs of packed fp32x2 accumulators
        unsigned long long acc[8][4];
        #pragma unroll
        for (int i = 0; i < 8; i++)
            #pragma unroll
            for (int j = 0; j < 4; j++) acc[i][j] = 0ull;

        // register double-buffer for code tiles
        float4 ra, rb;
        const int code0 = tid >> 2, kq0 = tid & 3;             // e = tid
        const int code1 = (tid + 256) >> 2, kq1 = (tid + 256) & 3;

        // prefetch stage 0
        ra = __ldg(cb4 + (size_t)(c0 + code0) * (ED / 4) + kq0);
        rb = __ldg(cb4 + (size_t)(c0 + code1) * (ED / 4) + kq1);
        {
            float* dst = bs;  // buf 0
            dst[(kq0 * 4 + 0) * BSS + code0] = ra.x;
            dst[(kq0 * 4 + 1) * BSS + code0] = ra.y;
            dst[(kq0 * 4 + 2) * BSS + code0] = ra.z;
            dst[(kq0 * 4 + 3) * BSS + code0] = ra.w;
            dst[(kq1 * 4 + 0) * BSS + code1] = rb.x;
            dst[(kq1 * 4 + 1) * BSS + code1] = rb.y;
            dst[(kq1 * 4 + 2) * BSS + code1] = rb.z;
            dst[(kq1 * 4 + 3) * BSS + code1] = rb.w;
        }
        __syncthreads();

        for (int s = 0; s < NSTG; s++) {
            if (s < NSTG - 1) {
                ra = __ldg(cb4 + (size_t)(c0 + code0) * (ED / 4) + (s + 1) * 4 + kq0);
                rb = __ldg(cb4 + (size_t)(c0 + code1) * (ED / 4) + (s + 1) * 4 + kq1);
            }
            const float* bcur = bs + (s & 1) * BK * BSS;
            const int kbase = s * BK;
            #pragma unroll
            for (int kk = 0; kk < BK; kk++) {
                const int k = kbase + kk;
                float a[8];
                float4 t;
                t = *(const float4*)&zs[k * BM + ty * 8];
                a[0] = t.x; a[1] = t.y; a[2] = t.z; a[3] = t.w;
                t = *(const float4*)&zs[k * BM + ty * 8 + 4];
                a[4] = t.x; a[5] = t.y; a[6] = t.z; a[7] = t.w;
                // b pairs come straight out of the 128-bit shared loads
                ulonglong2 tb0 = *(const ulonglong2*)&bcur[kk * BSS + tx * 8];
                ulonglong2 tb1 = *(const ulonglong2*)&bcur[kk * BSS + tx * 8 + 4];
                unsigned long long bp[4] = {tb0.x, tb0.y, tb1.x, tb1.y};
                #pragma unroll
                for (int i = 0; i < 8; i++) {
                    unsigned long long ap = pack2(a[i], a[i]);
                    #pragma unroll
                    for (int j = 0; j < 4; j++)
                        ffma2(acc[i][j], ap, bp[j]);
                }
            }
            __syncthreads();
            if (s < NSTG - 1) {
                float* dst = bs + ((s + 1) & 1) * BK * BSS;
                dst[(kq0 * 4 + 0) * BSS + code0] = ra.x;
                dst[(kq0 * 4 + 1) * BSS + code0] = ra.y;
                dst[(kq0 * 4 + 2) * BSS + code0] = ra.z;
                dst[(kq0 * 4 + 3) * BSS + code0] = ra.w;
                dst[(kq1 * 4 + 0) * BSS + code1] = rb.x;
                dst[(kq1 * 4 + 1) * BSS + code1] = rb.y;
                dst[(kq1 * 4 + 2) * BSS + code1] = rb.z;
                dst[(kq1 * 4 + 3) * BSS + code1] = rb.w;
                __syncthreads();
            }
        }

        // epilogue: d = fl(fl(A+B) - 2*dot), running argmin (first-index ties)
        #pragma unroll
        for (int i = 0; i < 8; i++) {
            #pragma unroll
            for (int j = 0; j < 4; j++) {
                float dlo, dhi;
                unpack2(dlo, dhi, acc[i][j]);
                float vlo = __fsub_rn(__fadd_rn(Aval[i], Bv[2 * j]),
                                      __fmul_rn(2.0f, dlo));
                float vhi = __fsub_rn(__fadd_rn(Aval[i], Bv[2 * j + 1]),
                                      __fmul_rn(2.0f, dhi));
                int col = c0 + tx * 8 + 2 * j;
                if (vlo < best[i]) { best[i] = vlo; bidx[i] = col; }
                if (vhi < best[i]) { best[i] = vhi; bidx[i] = col + 1; }
            }
        }
    }

    // cross-tx reduction: 16 lanes (same ty) live in one half-warp
    #pragma unroll
    for (int i = 0; i < 8; i++) {
        float v = best[i];
        int ix = bidx[i];
        #pragma unroll
        for (int off = 8; off > 0; off >>= 1) {
            float ov = __shfl_xor_sync(0xFFFFFFFFu, v, off);
            int   oi = __shfl_xor_sync(0xFFFFFFFFu, ix, off);
            if (ov < v || (ov == v && oi < ix)) { v = ov; ix = oi; }
        }
        if (tx == 0) sidx[ty * 8 + i] = ix;
    }
    __syncthreads();

    // fused gather: out[q0+r, :] = codebook[sidx[r], :]
    float4* out4 = (float4*)out;
    for (int e = tid; e < BM * (ED / 4); e += 256) {
        int r = e >> 6;
        int c = e & 63;
        out4[(size_t)(q0 + r) * (ED / 4) + c] =
            __ldg(cb4 + (size_t)sidx[r] * (ED / 4) + c);
    }
}

// ---------------------------------------------------------------------------
extern "C" void kernel_launch(void* const* d_in, const int* in_sizes, int n_in,
                              void* d_out, int out_size) {
    const float* z  = (const float*)d_in[0];   // [32,2048,256] f32
    const float* cb = (const float*)d_in[1];   // [4096,256] f32
    float* out = (float*)d_out;

    const int smem_bytes = (ED * BM + 2 * BK * BSS) * (int)sizeof(float);
    cudaFuncSetAttribute(vq_main, cudaFuncAttributeMaxDynamicSharedMemorySize,
                         smem_bytes);

    rowsq_z <<<NQ / 256, 256>>>((const float4*)z);
    rowsq_cb<<<NE / 256, 256>>>((const float4*)cb);
    vq_main <<<NQ / BM, 256, smem_bytes>>>(z, cb, out);
}

// round 3
// speedup vs baseline: 1.6553x; 1.6324x over previous
#include <cuda_runtime.h>
#include <cuda_bf16.h>
#include <float.h>
#include <stdint.h>

// Problem constants
#define NQ    65536
#define NE    4096
#define ED    256
#define CAND  64            // candidate slots per query
#define W_MARGIN 8e-4f      // collection window (rigorous bound ~2.1e-4)

// Scratch (no allocations allowed)
__device__ float g_A[NQ];
__device__ float g_B[NE];
__device__ int   g_cnt[NQ];
__device__ int   g_cand[NQ * CAND];

// ---------------------------------------------------------------------------
__device__ __forceinline__ unsigned cvt_tf32(float x) {
    unsigned r;
    asm("cvt.rna.tf32.f32 %0, %1;" : "=r"(r) : "f"(x));
    return r;
}

__device__ __forceinline__ void mma_tf32(float c[4],
                                         unsigned a0, unsigned a1,
                                         unsigned a2, unsigned a3,
                                         unsigned b0, unsigned b1) {
    asm volatile(
        "mma.sync.aligned.m16n8k8.row.col.f32.tf32.tf32.f32 "
        "{%0,%1,%2,%3}, {%4,%5,%6,%7}, {%8,%9}, {%0,%1,%2,%3};"
        : "+f"(c[0]), "+f"(c[1]), "+f"(c[2]), "+f"(c[3])
        : "r"(a0), "r"(a1), "r"(a2), "r"(a3), "r"(b0), "r"(b1));
}

// ---------------------------------------------------------------------------
// Row sums of squares — bit-exact reference order: fadd(fmul), sequential.
// ---------------------------------------------------------------------------
__global__ void rowsq_z(const float4* __restrict__ z4) {
    int n = blockIdx.x * blockDim.x + threadIdx.x;
    if (n >= NQ) return;
    const float4* p = z4 + (size_t)n * (ED / 4);
    float acc = 0.0f;
    #pragma unroll 8
    for (int i = 0; i < ED / 4; i++) {
        float4 v = __ldg(p + i);
        acc = __fadd_rn(acc, __fmul_rn(v.x, v.x));
        acc = __fadd_rn(acc, __fmul_rn(v.y, v.y));
        acc = __fadd_rn(acc, __fmul_rn(v.z, v.z));
        acc = __fadd_rn(acc, __fmul_rn(v.w, v.w));
    }
    g_A[n] = acc;
}

__global__ void rowsq_cb(const float4* __restrict__ c4) {
    int n = blockIdx.x * blockDim.x + threadIdx.x;
    if (n >= NE) return;
    const float4* p = c4 + (size_t)n * (ED / 4);
    float acc = 0.0f;
    #pragma unroll 8
    for (int i = 0; i < ED / 4; i++) {
        float4 v = __ldg(p + i);
        acc = __fadd_rn(acc, __fmul_rn(v.x, v.x));
        acc = __fadd_rn(acc, __fmul_rn(v.y, v.y));
        acc = __fadd_rn(acc, __fmul_rn(v.z, v.z));
        acc = __fadd_rn(acc, __fmul_rn(v.w, v.w));
    }
    g_B[n] = acc;
}

// ---------------------------------------------------------------------------
// Phase 1: tf32 tensor-core screening. CTA = 128 queries (8 warps x 16q),
// loops 64 code-tiles of 64. Collects all codes with s = B - 2*dot within
// W_MARGIN of the per-query running min (provable superset of exact argmin).
//
// smem: zsA (A fragments, pre-swizzled)  8w*32kc*4r*32lane = 32768 f (128KB)
//       sB  (B fragments, pre-swizzled) 32kc*16r*32lane    = 16384 f ( 64KB)
//       scnt[128] counters
// ---------------------------------------------------------------------------
#define SCREEN_SMEM ((32768 + 16384) * 4 + 128 * 4)

__global__ void __launch_bounds__(256, 1)
vq_screen(const float* __restrict__ z, const float* __restrict__ cb) {
    extern __shared__ float sm[];
    float*    zsA  = sm;
    float*    sB   = sm + 32768;
    int*      scnt = (int*)(sm + 32768 + 16384);
    unsigned* zsAu = (unsigned*)zsA;
    unsigned* sBu  = (unsigned*)sB;

    const int tid  = threadIdx.x;
    const int lane = tid & 31;
    const int w    = tid >> 5;
    const int q0   = blockIdx.x * 128;

    const float4* z4  = (const float4*)z;
    const float4* cb4 = (const float4*)cb;

    if (tid < 128) scnt[tid] = 0;

    // ---- stage z (tf32, A-fragment swizzle) ----
    // a_r for (q,k): r = khalf*2 + qhi; lane = qlow*4 + k1
    for (int e = tid; e < 128 * 64; e += 256) {
        int q = e >> 6;
        int f = e & 63;               // float4 idx; k = 4f
        float4 v = __ldg(z4 + (size_t)(q0 + q) * 64 + f);
        uint4 t;
        t.x = cvt_tf32(v.x); t.y = cvt_tf32(v.y);
        t.z = cvt_tf32(v.z); t.w = cvt_tf32(v.w);
        int wq = q >> 4, qin = q & 15;
        int kc = f >> 1, khalf = f & 1;
        int qlow = qin & 7, qhi = qin >> 3;
        int r = khalf * 2 + qhi;
        int l = qlow * 4;
        *(uint4*)&zsAu[((wq * 32 + kc) * 4 + r) * 32 + l] = t;
    }

    float runmin_a = FLT_MAX, runmin_b = FLT_MAX;
    const int qla = (w << 4) + (lane >> 2);   // local query for c[.][0..1]
    __syncthreads();

    for (int nt = 0; nt < 64; nt++) {
        const int c0g = nt * 64;

        // ---- stage cb tile (tf32, B-fragment swizzle) ----
        // b at (k,n): r = khalf*8 + j; lane = nin*4 + k1
        for (int e = tid; e < 64 * 64; e += 256) {
            int n = e >> 6, f = e & 63;
            float4 v = __ldg(cb4 + (size_t)(c0g + n) * 64 + f);
            uint4 t;
            t.x = cvt_tf32(v.x); t.y = cvt_tf32(v.y);
            t.z = cvt_tf32(v.z); t.w = cvt_tf32(v.w);
            int kc = f >> 1, khalf = f & 1;
            int j = n >> 3, nin = n & 7;
            int r = khalf * 8 + j;
            int l = nin * 4;
            *(uint4*)&sBu[(kc * 16 + r) * 32 + l] = t;
        }
        __syncthreads();

        // ---- MMA: 16 queries x 64 codes per warp ----
        float c[8][4];
        #pragma unroll
        for (int j = 0; j < 8; j++)
            #pragma unroll
            for (int t = 0; t < 4; t++) c[j][t] = 0.0f;

        for (int kc = 0; kc < 32; kc++) {
            const unsigned* za = &zsAu[((w * 32 + kc) * 4) * 32 + lane];
            unsigned a0 = za[0], a1 = za[32], a2 = za[64], a3 = za[96];
            const unsigned* bb = &sBu[(kc * 16) * 32 + lane];
            #pragma unroll
            for (int j = 0; j < 8; j++) {
                unsigned b0 = bb[j * 32];
                unsigned b1 = bb[(8 + j) * 32];
                mma_tf32(c[j], a0, a1, a2, a3, b0, b1);
            }
        }

        // ---- epilogue: tile mins, running min, candidate push ----
        float tmin_a = FLT_MAX, tmin_b = FLT_MAX;
        #pragma unroll
        for (int j = 0; j < 8; j++) {
            int cc = c0g + j * 8 + ((lane & 3) << 1);
            float B0 = __ldg(&g_B[cc]);
            float B1 = __ldg(&g_B[cc + 1]);
            float s0 = B0 - 2.0f * c[j][0];
            float s1 = B1 - 2.0f * c[j][1];
            float s2 = B0 - 2.0f * c[j][2];
            float s3 = B1 - 2.0f * c[j][3];
            tmin_a = fminf(tmin_a, fminf(s0, s1));
            tmin_b = fminf(tmin_b, fminf(s2, s3));
        }
        float ga = tmin_a, gb = tmin_b;
        ga = fminf(ga, __shfl_xor_sync(~0u, ga, 1));
        ga = fminf(ga, __shfl_xor_sync(~0u, ga, 2));
        gb = fminf(gb, __shfl_xor_sync(~0u, gb, 1));
        gb = fminf(gb, __shfl_xor_sync(~0u, gb, 2));
        runmin_a = fminf(runmin_a, ga);
        runmin_b = fminf(runmin_b, gb);
        const float thra = runmin_a + W_MARGIN;
        const float thrb = runmin_b + W_MARGIN;

        bool hit = (tmin_a <= thra) || (tmin_b <= thrb);
        if (__ballot_sync(~0u, hit)) {
            #pragma unroll
            for (int j = 0; j < 8; j++) {
                int cc = c0g + j * 8 + ((lane & 3) << 1);
                float B0 = __ldg(&g_B[cc]);
                float B1 = __ldg(&g_B[cc + 1]);
                float s0 = B0 - 2.0f * c[j][0];
                float s1 = B1 - 2.0f * c[j][1];
                float s2 = B0 - 2.0f * c[j][2];
                float s3 = B1 - 2.0f * c[j][3];
                if (s0 <= thra) {
                    int sl = atomicAdd(&scnt[qla], 1);
                    if (sl < CAND) g_cand[(size_t)(q0 + qla) * CAND + sl] = cc;
                }
                if (s1 <= thra) {
                    int sl = atomicAdd(&scnt[qla], 1);
                    if (sl < CAND) g_cand[(size_t)(q0 + qla) * CAND + sl] = cc + 1;
                }
                if (s2 <= thrb) {
                    int sl = atomicAdd(&scnt[qla + 8], 1);
                    if (sl < CAND) g_cand[(size_t)(q0 + qla + 8) * CAND + sl] = cc;
                }
                if (s3 <= thrb) {
                    int sl = atomicAdd(&scnt[qla + 8], 1);
                    if (sl < CAND) g_cand[(size_t)(q0 + qla + 8) * CAND + sl] = cc + 1;
                }
            }
        }
        __syncthreads();
    }

    for (int i = tid; i < 128; i += 256) g_cnt[q0 + i] = scnt[i];
}

// ---------------------------------------------------------------------------
// Phase 2: exact verification. One warp per query. For each candidate,
// recompute the reference-exact chain: dot via fmaf k=0..255 sequential,
// d = fl(fl(A+B) - 2*dot); argmin with first-index tie-break; fused gather.
// Overflow (cnt > CAND): full exact scan of all 4096 codes.
// ---------------------------------------------------------------------------
__global__ void __launch_bounds__(256, 2)
vq_exact(const float* __restrict__ z, const float* __restrict__ cb,
         float* __restrict__ out) {
    const int q    = blockIdx.x * 8 + (threadIdx.x >> 5);
    const int lane = threadIdx.x & 31;
    if (q >= NQ) return;

    int cnt = g_cnt[q];
    const bool ovf = (cnt > CAND);
    const int ncand = ovf ? NE : cnt;

    const float A = g_A[q];
    const float4* z4  = (const float4*)z + (size_t)q * 64;
    const float4* cb4 = (const float4*)cb;

    float bd = FLT_MAX;
    int   bc = 0x7fffffff;

    for (int i = lane; i < ncand; i += 32) {
        int cdx = ovf ? i : g_cand[(size_t)q * CAND + i];
        const float4* crow = cb4 + (size_t)cdx * 64;
        float dot = 0.0f;
        #pragma unroll 8
        for (int f = 0; f < 64; f++) {
            float4 zv = __ldg(z4 + f);
            float4 cv = __ldg(crow + f);
            dot = fmaf(zv.x, cv.x, dot);
            dot = fmaf(zv.y, cv.y, dot);
            dot = fmaf(zv.z, cv.z, dot);
            dot = fmaf(zv.w, cv.w, dot);
        }
        float d = __fsub_rn(__fadd_rn(A, __ldg(&g_B[cdx])),
                            __fmul_rn(2.0f, dot));
        if (d < bd || (d == bd && cdx < bc)) { bd = d; bc = cdx; }
    }

    #pragma unroll
    for (int off = 16; off; off >>= 1) {
        float od = __shfl_xor_sync(~0u, bd, off);
        int   oc = __shfl_xor_sync(~0u, bc, off);
        if (od < bd || (od == bd && oc < bc)) { bd = od; bc = oc; }
    }
    if (bc == 0x7fffffff) bc = 0;   // safety (cnt>=1 guaranteed)

    float4* out4 = (float4*)out + (size_t)q * 64;
    const float4* win = cb4 + (size_t)bc * 64;
    #pragma unroll
    for (int f = lane; f < 64; f += 32) out4[f] = __ldg(win + f);
}

// ---------------------------------------------------------------------------
extern "C" void kernel_launch(void* const* d_in, const int* in_sizes, int n_in,
                              void* d_out, int out_size) {
    const float* z  = (const float*)d_in[0];   // [32,2048,256] f32
    const float* cb = (const float*)d_in[1];   // [4096,256] f32
    float* out = (float*)d_out;

    cudaFuncSetAttribute(vq_screen, cudaFuncAttributeMaxDynamicSharedMemorySize,
                         SCREEN_SMEM);

    rowsq_z  <<<NQ / 256, 256>>>((const float4*)z);
    rowsq_cb <<<NE / 256, 256>>>((const float4*)cb);
    vq_screen<<<NQ / 128, 256, SCREEN_SMEM>>>(z, cb);
    vq_exact <<<NQ / 8, 256>>>(z, cb, out);
}

// round 5
// speedup vs baseline: 4.1306x; 2.4955x over previous
#include <cuda_runtime.h>
#include <cuda_bf16.h>
#include <float.h>
#include <stdint.h>

#define NQ    65536
#define NE    4096
#define ED    256
#define CAND  64
#define W_MARGIN 1.5e-3f

#define QB     256          // queries per CTA
#define TN     64           // codes per tile
#define NTILES (NE / TN)    // 64

// Scratch (no allocations allowed)
__device__ float g_A[NQ];
__device__ float g_B[NE];
__device__ int   g_cnt[NQ];
__device__ int   g_cand[NQ * CAND];

// ---------------------------------------------------------------------------
// helpers (base-ISA only: no tcgen05 — harness PTX target is sm_103 base)
// ---------------------------------------------------------------------------
__device__ __forceinline__ uint32_t smem_u32(const void* p) {
    uint32_t a;
    asm("{ .reg .u64 t; cvta.to.shared.u64 t, %1; cvt.u32.u64 %0, t; }"
        : "=r"(a) : "l"(p));
    return a;
}
__device__ __forceinline__ void mbar_init(uint32_t a, uint32_t n) {
    asm volatile("mbarrier.init.shared.b64 [%0], %1;" :: "r"(a), "r"(n) : "memory");
}
__device__ __forceinline__ void mbar_arrive(uint32_t a) {
    asm volatile("mbarrier.arrive.shared.b64 _, [%0];" :: "r"(a) : "memory");
}
__device__ __forceinline__ void mbar_wait(uint32_t a, uint32_t ph) {
    uint32_t done;
    asm volatile("{\n\t.reg .pred p;\n\t"
                 "mbarrier.try_wait.parity.acquire.cta.shared::cta.b64 p, [%1], %2;\n\t"
                 "selp.b32 %0,1,0,p;\n\t}"
                 : "=r"(done) : "r"(a), "r"(ph) : "memory");
    if (!done) {
        asm volatile("{\n\t.reg .pred P1;\n\t"
                     "WL_%=:\n\t"
                     "mbarrier.try_wait.parity.acquire.cta.shared::cta.b64 P1, [%0], %1, 0x989680;\n\t"
                     "@P1 bra.uni WD_%=;\n\t"
                     "bra.uni WL_%=;\n\t"
                     "WD_%=:\n\t}"
                     :: "r"(a), "r"(ph) : "memory");
    }
}
// pack two f32 -> bf16x2 (rne): lo in low half, hi in high half
__device__ __forceinline__ uint32_t pk2(float lo, float hi) {
    uint32_t r;
    asm("cvt.rn.bf16x2.f32 %0, %1, %2;" : "=r"(r) : "f"(hi), "f"(lo));
    return r;
}
__device__ __forceinline__ void ldsm4(uint32_t r[4], uint32_t addr) {
    asm volatile("ldmatrix.sync.aligned.m8n8.x4.shared.b16 {%0,%1,%2,%3}, [%4];"
                 : "=r"(r[0]), "=r"(r[1]), "=r"(r[2]), "=r"(r[3]) : "r"(addr));
}
__device__ __forceinline__ void mma_bf16(float c[4], const uint32_t a[4],
                                         uint32_t b0, uint32_t b1) {
    asm volatile("mma.sync.aligned.m16n8k16.row.col.f32.bf16.bf16.f32 "
                 "{%0,%1,%2,%3}, {%4,%5,%6,%7}, {%8,%9}, {%0,%1,%2,%3};"
                 : "+f"(c[0]), "+f"(c[1]), "+f"(c[2]), "+f"(c[3])
                 : "r"(a[0]), "r"(a[1]), "r"(a[2]), "r"(a[3]), "r"(b0), "r"(b1));
}

// ---------------------------------------------------------------------------
// Row sums of squares — bit-exact reference order: fadd(fmul), sequential.
// ---------------------------------------------------------------------------
__global__ void rowsq_z(const float4* __restrict__ z4) {
    int n = blockIdx.x * blockDim.x + threadIdx.x;
    if (n >= NQ) return;
    const float4* p = z4 + (size_t)n * (ED / 4);
    float acc = 0.0f;
    #pragma unroll 8
    for (int i = 0; i < ED / 4; i++) {
        float4 v = __ldg(p + i);
        acc = __fadd_rn(acc, __fmul_rn(v.x, v.x));
        acc = __fadd_rn(acc, __fmul_rn(v.y, v.y));
        acc = __fadd_rn(acc, __fmul_rn(v.z, v.z));
        acc = __fadd_rn(acc, __fmul_rn(v.w, v.w));
    }
    g_A[n] = acc;
}

__global__ void rowsq_cb(const float4* __restrict__ c4) {
    int n = blockIdx.x * blockDim.x + threadIdx.x;
    if (n >= NE) return;
    const float4* p = c4 + (size_t)n * (ED / 4);
    float acc = 0.0f;
    #pragma unroll 8
    for (int i = 0; i < ED / 4; i++) {
        float4 v = __ldg(p + i);
        acc = __fadd_rn(acc, __fmul_rn(v.x, v.x));
        acc = __fadd_rn(acc, __fmul_rn(v.y, v.y));
        acc = __fadd_rn(acc, __fmul_rn(v.z, v.z));
        acc = __fadd_rn(acc, __fmul_rn(v.w, v.w));
    }
    g_B[n] = acc;
}

// ---------------------------------------------------------------------------
// Phase 1: bf16 mma.sync screening, warp-specialized.
// CTA = 256 queries (A bf16 [256][256] persistent in smem, XOR-swizzled).
// 8 compute warps, each 32q x 64codes; 2 producer warps double-buffer the
// 64-code B tile (bf16, 32KB) + its row-sumsq via an mbarrier ring.
// Collects codes with s = A+B-2*dot <= runmin + W (superset of exact argmin).
// ---------------------------------------------------------------------------
// smem layout (1KB-aligned base):
//   A:    [0, 131072)            256 rows x 512B
//   B[2]: [131072, 196608)       2 x (64 rows x 512B)
//   bsq:  [196608, 197120)       2 x 64 floats
//   cnt:  [197120, 198144)       256 ints
//   mbar: [198144, 198176)       full0 full1 empty0 empty1
#define SA_OFF   0
#define SB_OFF   131072
#define BSQ_OFF  196608
#define CNT_OFF  197120
#define MB_OFF   198144
#define SCREEN_SMEM (198176 + 1024)

__global__ void __launch_bounds__(320, 1)
vq_screen(const float* __restrict__ z, const float* __restrict__ cb) {
    extern __shared__ char smraw[];
    char* smem = (char*)(((uintptr_t)smraw + 1023) & ~(uintptr_t)1023);
    const uint32_t smb = smem_u32(smem);

    const int tid  = threadIdx.x;
    const int lane = tid & 31;
    const int w    = tid >> 5;           // 0..9
    const int q0   = blockIdx.x * QB;

    float* bsq = (float*)(smem + BSQ_OFF);
    int*   cnt = (int*)(smem + CNT_OFF);
    const uint32_t mb = smb + MB_OFF;    // +0/+8 full[2], +16/+24 empty[2]

    const float4* z4  = (const float4*)z;
    const float4* cb4 = (const float4*)cb;

    if (tid == 0) {
        mbar_init(mb + 0, 64);  mbar_init(mb + 8, 64);    // full: 64 producer thr
        mbar_init(mb + 16, 256); mbar_init(mb + 24, 256); // empty: 256 consumer thr
    }
    if (tid < 256) cnt[tid] = 0;

    // ---- stage A: f32 -> bf16 (rne), rows of 512B, 16B-unit XOR swizzle ----
    for (int e = tid; e < QB * 32; e += 320) {
        int q = e >> 5, c = e & 31;
        float4 v0 = __ldg(z4 + (size_t)(q0 + q) * 64 + 2 * c);
        float4 v1 = __ldg(z4 + (size_t)(q0 + q) * 64 + 2 * c + 1);
        uint4 t;
        t.x = pk2(v0.x, v0.y); t.y = pk2(v0.z, v0.w);
        t.z = pk2(v1.x, v1.y); t.w = pk2(v1.z, v1.w);
        *(uint4*)(smem + SA_OFF + q * 512 + ((c ^ (q & 7)) << 4)) = t;
    }
    __syncthreads();

    if (w >= 8) {
        // ---------------- producers (warps 8,9) ----------------
        const int t = tid - 256;         // 0..63
        for (int nt = 0; nt < NTILES; nt++) {
            const int b = nt & 1;
            if (nt >= 2) mbar_wait(mb + 16 + b * 8, ((nt - 2) >> 1) & 1);
            char* bp = smem + SB_OFF + b * 32768;
            const int n0t = nt * TN;
            #pragma unroll 4
            for (int e = t; e < TN * 32; e += 64) {
                int n = e >> 5, c = e & 31;
                float4 v0 = __ldg(cb4 + (size_t)(n0t + n) * 64 + 2 * c);
                float4 v1 = __ldg(cb4 + (size_t)(n0t + n) * 64 + 2 * c + 1);
                uint4 tt;
                tt.x = pk2(v0.x, v0.y); tt.y = pk2(v0.z, v0.w);
                tt.z = pk2(v1.x, v1.y); tt.w = pk2(v1.z, v1.w);
                *(uint4*)(bp + n * 512 + ((c ^ (n & 7)) << 4)) = tt;
            }
            bsq[b * 64 + t] = __ldg(&g_B[n0t + t]);
            mbar_arrive(mb + b * 8);
        }
    } else {
        // ---------------- consumers (warps 0-7): 32q x 64c each ----------------
        float Aq[4], runmin[4];
        int qloc[4];
        #pragma unroll
        for (int i = 0; i < 4; i++) {
            qloc[i] = w * 32 + i * 8 + (lane >> 2);
            Aq[i] = g_A[q0 + qloc[i]];
            runmin[i] = FLT_MAX;
        }

        for (int nt = 0; nt < NTILES; nt++) {
            const int b = nt & 1;
            mbar_wait(mb + b * 8, (nt >> 1) & 1);

            float acc[2][8][4];
            #pragma unroll
            for (int mi = 0; mi < 2; mi++)
                #pragma unroll
                for (int j = 0; j < 8; j++)
                    #pragma unroll
                    for (int p = 0; p < 4; p++) acc[mi][j][p] = 0.0f;

            const uint32_t sb_base = smb + SB_OFF + b * 32768;
            #pragma unroll
            for (int kc = 0; kc < 16; kc++) {
                uint32_t a[2][4];
                #pragma unroll
                for (int mi = 0; mi < 2; mi++) {
                    int qr = w * 32 + mi * 16 + (lane & 15);
                    uint32_t ad = smb + SA_OFF + qr * 512 +
                        ((((kc << 1) | (lane >> 4)) ^ (qr & 7)) << 4);
                    ldsm4(a[mi], ad);
                }
                uint32_t bf[4][4];
                #pragma unroll
                for (int jp = 0; jp < 4; jp++) {
                    int nr = jp * 16 + (lane & 7) + ((lane & 16) >> 1);
                    int cc = (kc << 1) | ((lane >> 3) & 1);
                    uint32_t ad = sb_base + nr * 512 + ((cc ^ (nr & 7)) << 4);
                    ldsm4(bf[jp], ad);
                }
                #pragma unroll
                for (int mi = 0; mi < 2; mi++)
                    #pragma unroll
                    for (int jp = 0; jp < 4; jp++) {
                        mma_bf16(acc[mi][jp * 2],     a[mi], bf[jp][0], bf[jp][1]);
                        mma_bf16(acc[mi][jp * 2 + 1], a[mi], bf[jp][2], bf[jp][3]);
                    }
            }

            // B row-sumsq for this lane's 16 columns, then release buffer
            float Bn[16];
            #pragma unroll
            for (int j = 0; j < 8; j++) {
                Bn[2 * j]     = bsq[b * 64 + j * 8 + (lane & 3) * 2];
                Bn[2 * j + 1] = bsq[b * 64 + j * 8 + (lane & 3) * 2 + 1];
            }
            mbar_arrive(mb + 16 + b * 8);

            const int n0t = nt * TN;
            float thr[4];
            #pragma unroll
            for (int i = 0; i < 4; i++) {
                const int mi = i >> 1, rh = i & 1;
                float m = FLT_MAX;
                #pragma unroll
                for (int j = 0; j < 8; j++) {
                    float v0 = fmaf(-2.0f, acc[mi][j][rh * 2],     Aq[i] + Bn[2 * j]);
                    float v1 = fmaf(-2.0f, acc[mi][j][rh * 2 + 1], Aq[i] + Bn[2 * j + 1]);
                    m = fminf(m, fminf(v0, v1));
                }
                m = fminf(m, __shfl_xor_sync(~0u, m, 1));
                m = fminf(m, __shfl_xor_sync(~0u, m, 2));
                runmin[i] = fminf(runmin[i], m);
                thr[i] = runmin[i] + W_MARGIN;
            }
            #pragma unroll
            for (int i = 0; i < 4; i++) {
                const int mi = i >> 1, rh = i & 1;
                #pragma unroll
                for (int j = 0; j < 8; j++) {
                    #pragma unroll
                    for (int p = 0; p < 2; p++) {
                        float v = fmaf(-2.0f, acc[mi][j][rh * 2 + p],
                                       Aq[i] + Bn[2 * j + p]);
                        if (v <= thr[i]) {
                            int sl = atomicAdd(&cnt[qloc[i]], 1);
                            if (sl < CAND)
                                g_cand[(size_t)(q0 + qloc[i]) * CAND + sl] =
                                    n0t + j * 8 + (lane & 3) * 2 + p;
                        }
                    }
                }
            }
        }
    }

    __syncthreads();
    if (tid < 256) g_cnt[q0 + tid] = cnt[tid];
}

// ---------------------------------------------------------------------------
// Phase 2: exact verification. One warp per query, reference-exact chain:
// dot via fmaf k=0..255 sequential, d = fl(fl(A+B) - 2*dot); first-index
// tie-break; fused winner gather. Overflow -> full scan.
// ---------------------------------------------------------------------------
__global__ void __launch_bounds__(256, 2)
vq_exact(const float* __restrict__ z, const float* __restrict__ cb,
         float* __restrict__ out) {
    const int q    = blockIdx.x * 8 + (threadIdx.x >> 5);
    const int lane = threadIdx.x & 31;
    if (q >= NQ) return;

    int cnt = g_cnt[q];
    const bool ovf = (cnt > CAND);
    const int ncand = ovf ? NE : cnt;

    const float A = g_A[q];
    const float4* z4  = (const float4*)z + (size_t)q * 64;
    const float4* cb4 = (const float4*)cb;

    float bd = FLT_MAX;
    int   bc = 0x7fffffff;

    for (int i = lane; i < ncand; i += 32) {
        int cdx = ovf ? i : g_cand[(size_t)q * CAND + i];
        const float4* crow = cb4 + (size_t)cdx * 64;
        float dot = 0.0f;
        #pragma unroll 8
        for (int f = 0; f < 64; f++) {
            float4 zv = __ldg(z4 + f);
            float4 cv = __ldg(crow + f);
            dot = fmaf(zv.x, cv.x, dot);
            dot = fmaf(zv.y, cv.y, dot);
            dot = fmaf(zv.z, cv.z, dot);
            dot = fmaf(zv.w, cv.w, dot);
        }
        float d = __fsub_rn(__fadd_rn(A, __ldg(&g_B[cdx])),
                            __fmul_rn(2.0f, dot));
        if (d < bd || (d == bd && cdx < bc)) { bd = d; bc = cdx; }
    }

    #pragma unroll
    for (int off = 16; off; off >>= 1) {
        float od = __shfl_xor_sync(~0u, bd, off);
        int   oc = __shfl_xor_sync(~0u, bc, off);
        if (od < bd || (od == bd && oc < bc)) { bd = od; bc = oc; }
    }
    if (bc == 0x7fffffff) bc = 0;

    float4* out4 = (float4*)out + (size_t)q * 64;
    const float4* win = cb4 + (size_t)bc * 64;
    #pragma unroll
    for (int f = lane; f < 64; f += 32) out4[f] = __ldg(win + f);
}

// ---------------------------------------------------------------------------
extern "C" void kernel_launch(void* const* d_in, const int* in_sizes, int n_in,
                              void* d_out, int out_size) {
    const float* z  = (const float*)d_in[0];   // [32,2048,256] f32
    const float* cb = (const float*)d_in[1];   // [4096,256] f32
    float* out = (float*)d_out;

    cudaFuncSetAttribute(vq_screen, cudaFuncAttributeMaxDynamicSharedMemorySize,
                         SCREEN_SMEM);

    rowsq_z  <<<NQ / 256, 256>>>((const float4*)z);
    rowsq_cb <<<NE / 256, 256>>>((const float4*)cb);
    vq_screen<<<NQ / QB, 320, SCREEN_SMEM>>>(z, cb);
    vq_exact <<<NQ / 8, 256>>>(z, cb, out);
}